// round 16
// baseline (speedup 1.0000x reference)
// BitNet-style FFN on GB300 — sm_103 baseline-ISA build (tcgen05 rejected by the
// harness's ptxas). cp.async + ldmatrix + mma.sync.m16n8k16.f32.f16.f16.f32.
//   out = gelu_exact(x @ T(W1)^T + b1) @ T(W2)^T + b2,  T() = absmean ternary {-1,0,1}
// Ternary weights EXACT in fp16; x/H fp16, fp32 accumulators -> rel_err ~3e-4.
// R16: per-kk accounting from R15 — single-buffered GEMM1 ran ~0.92x SERIAL
//      (LDSM burst 384 + MMA burst 512 ≈ 822 observed); DBUF GEMM2 ran 363 vs
//      serial 512 (real overlap). The lever is fragment double-buffering, not
//      occupancy. So GEMM1 adopts GEMM2's exact proven config: CTA 64x128,
//      warp 32x32, BK=128, 2 stages, DBUF, 2 CTAs/SM (regs ~110). Bonus: grid
//      4096 CTAs = 13.8 waves (1.2% tail).

#include <cuda_runtime.h>
#include <cuda_fp16.h>
#include <cstdint>

#define EMB 1024
#define FF 4096
#define NTOK 8192
#define WN_ (FF * EMB)
#define XN_ (NTOK * EMB)

// ---------------- device-global scratch (allocation-free rule) ----------------
__device__ __align__(16) __half g_Xh[(size_t)NTOK * EMB];   // 16 MB
__device__ __align__(16) __half g_W1t[(size_t)FF * EMB];    // 8 MB
__device__ __align__(16) __half g_W2t[(size_t)FF * EMB];    // 8 MB
__device__ __align__(16) __half g_H[(size_t)NTOK * FF];     // 64 MB
__device__ float g_partial[2048];
__device__ float g_scale[2];

// ---------------- PTX helpers ----------------
__device__ __forceinline__ uint32_t smem_u32(const void* p) {
    uint32_t a;
    asm("{ .reg .u64 t; cvta.to.shared.u64 t, %1; cvt.u32.u64 %0, t; }" : "=r"(a) : "l"(p));
    return a;
}

#define CP16(dst, src) \
    asm volatile("cp.async.cg.shared.global [%0], [%1], 16;" \
                 :: "r"((uint32_t)(dst)), "l"(__cvta_generic_to_global(src)) : "memory")
#define CP_COMMIT()  asm volatile("cp.async.commit_group;" ::: "memory")
#define CP_WAIT1()   asm volatile("cp.async.wait_group 1;" ::: "memory")

#define LDSM4(r0, r1, r2, r3, addr) \
    asm volatile("ldmatrix.sync.aligned.m8n8.x4.shared.b16 {%0,%1,%2,%3}, [%4];" \
                 : "=r"(r0), "=r"(r1), "=r"(r2), "=r"(r3) : "r"(addr))

#define MMA16816F(d, a0, a1, a2, a3, b0, b1) \
    asm("mma.sync.aligned.m16n8k16.row.col.f32.f16.f16.f32 " \
        "{%0,%1,%2,%3}, {%4,%5,%6,%7}, {%8,%9}, {%0,%1,%2,%3};" \
        : "+f"((d)[0]), "+f"((d)[1]), "+f"((d)[2]), "+f"((d)[3]) \
        : "r"(a0), "r"(a1), "r"(a2), "r"(a3), "r"(b0), "r"(b1))

// ---------------- fused GEMM + epilogue ----------------
// 8 warps (TPB=256), 2 CTAs/SM. (BM/WM)*(BN/WN) must == 8. NC must be >= 2.
// Pipeline invariant: chunks i, i+1 in flight at head of iteration i (2 groups);
// chunk j lives in stage j % NST. DBUF = double-buffered fragments.
// GELU=true : A=g_Xh [8192,1024], B=g_W1t [4096,1024], out=g_H (fp16), +b1, erf-GELU
// GELU=false: A=g_H  [8192,4096], B=g_W2t [1024,4096], out=out_f (fp32), +b2
template <int BM, int BN, int WM, int WN, int BK, int NST, bool DBUF, bool GELU>
__global__ void __launch_bounds__(256, 2)
ffn_gemm(const float* __restrict__ bias, float* __restrict__ out_f) {
    constexpr int TPB = 256;
    constexpr int ROWB = BK * 2;              // bytes per smem row
    constexpr int SEGS = BK / 8;              // 16B segs per row
    constexpr int A_BYTES = BM * ROWB;
    constexpr int B_BYTES = BN * ROWB;
    constexpr int STG_BYTES = A_BYTES + B_BYTES;
    constexpr int SM_TILES = 2048;
    constexpr int MT = WM / 16, PT = WN / 16, NT = WN / 8;
    constexpr int MW_CNT = BM / WM;
    constexpr int NK = BK / 16;               // k16 phases per chunk
    constexpr int K = GELU ? EMB : FF;
    constexpr int Npar = GELU ? FF : EMB;
    constexpr int NC = K / BK;
    static_assert(NC >= 2, "pipeline needs >= 2 chunks");

    extern __shared__ __align__(1024) uint8_t smem_raw[];
    uint32_t sb = smem_u32(smem_raw);
    const int tid = threadIdx.x;
    const int lane = tid & 31, warp = tid >> 5;
    const int wm = warp % MW_CNT;
    const int wn = warp / MW_CNT;
    const int m0 = blockIdx.y * BM;
    const int n0 = blockIdx.x * BN;

    const __half* A = GELU ? g_Xh : g_H;
    const __half* B = GELU ? g_W1t : g_W2t;

    float* bias_s = reinterpret_cast<float*>(smem_raw);
    for (int i = tid; i < BN; i += TPB) bias_s[i] = bias[n0 + i];

    // ldmatrix lane -> row-offset / k-half mapping (validated R5/R7)
    const int a_roff = (lane & 7) + ((lane >> 3) & 1) * 8;
    const int a_hi   = (lane >> 4) & 1;
    const int b_noff = (lane & 7) + ((lane >> 4) & 1) * 8;
    const int b_hi   = (lane >> 3) & 1;

    float acc[MT][NT][4];
    #pragma unroll
    for (int mt = 0; mt < MT; mt++)
        #pragma unroll
        for (int nt = 0; nt < NT; nt++)
            #pragma unroll
            for (int e = 0; e < 4; e++) acc[mt][nt][e] = 0.f;

    uint32_t a_rowb[MT]; int a_rc[MT];
    #pragma unroll
    for (int mt = 0; mt < MT; mt++) {
        int r = wm * WM + mt * 16 + a_roff;
        a_rowb[mt] = r * ROWB; a_rc[mt] = r & 7;
    }
    uint32_t b_rowb[PT]; int b_rc[PT];
    #pragma unroll
    for (int p = 0; p < PT; p++) {
        int r = wn * WN + p * 16 + b_noff;
        b_rowb[p] = r * ROWB; b_rc[p] = r & 7;
    }

    // tile loader: SEGS 16B segs/row; swizzle seg' = seg ^ (row & 7)
    auto load_tile = [&](int stage, int kc) {
        uint32_t sa = sb + SM_TILES + stage * STG_BYTES;
        uint32_t sB = sa + A_BYTES;
        #pragma unroll
        for (int t = 0; t < BM * SEGS / TPB; t++) {
            int i = tid + t * TPB;
            int r = i / SEGS, s = i % SEGS;
            uint32_t dst = sa + r * ROWB + ((s ^ (r & 7)) << 4);
            CP16(dst, A + (size_t)(m0 + r) * K + kc + s * 8);
        }
        #pragma unroll
        for (int t = 0; t < BN * SEGS / TPB; t++) {
            int i = tid + t * TPB;
            int r = i / SEGS, s = i % SEGS;
            uint32_t dst = sB + r * ROWB + ((s ^ (r & 7)) << 4);
            CP16(dst, B + (size_t)(n0 + r) * K + kc + s * 8);
        }
    };

    // prologue: chunks 0 and 1 in flight (2 groups) — pipeline invariant
    load_tile(0, 0);        CP_COMMIT();
    load_tile(1 % NST, BK); CP_COMMIT();

    for (int i = 0; i < NC; i++) {
        CP_WAIT1();        // retire chunk i's group (chunk i+1 stays in flight)
        __syncthreads();   // chunk i visible CTA-wide; prior readers of the
                           // stage we're about to refill are done
        uint32_t sa = sb + SM_TILES + (i % NST) * STG_BYTES;
        uint32_t sB = sa + A_BYTES;

        if (NST >= 3) {    // free stage exists: prefetch chunk i+2 now
            int pf = i + 2;
            if (pf < NC) load_tile(pf % NST, pf * BK);
            CP_COMMIT();
        }

        if constexpr (DBUF) {
            uint32_t ar[2][MT][4], br[2][PT][4];
            #pragma unroll
            for (int mt = 0; mt < MT; mt++) {
                uint32_t ad = sa + a_rowb[mt] + ((a_hi ^ a_rc[mt]) << 4);
                LDSM4(ar[0][mt][0], ar[0][mt][1], ar[0][mt][2], ar[0][mt][3], ad);
            }
            #pragma unroll
            for (int p = 0; p < PT; p++) {
                uint32_t bd = sB + b_rowb[p] + ((b_hi ^ b_rc[p]) << 4);
                LDSM4(br[0][p][0], br[0][p][1], br[0][p][2], br[0][p][3], bd);
            }
            #pragma unroll
            for (int kk = 0; kk < NK; kk++) {
                const int cb = kk & 1, nb = cb ^ 1;
                if (kk < NK - 1) {
                    const int s = 2 * (kk + 1);
                    #pragma unroll
                    for (int mt = 0; mt < MT; mt++) {
                        uint32_t ad = sa + a_rowb[mt] + (((s + a_hi) ^ a_rc[mt]) << 4);
                        LDSM4(ar[nb][mt][0], ar[nb][mt][1], ar[nb][mt][2], ar[nb][mt][3], ad);
                    }
                    #pragma unroll
                    for (int p = 0; p < PT; p++) {
                        uint32_t bd = sB + b_rowb[p] + (((s + b_hi) ^ b_rc[p]) << 4);
                        LDSM4(br[nb][p][0], br[nb][p][1], br[nb][p][2], br[nb][p][3], bd);
                    }
                }
                if (NST == 2 && kk == NK - 1) {
                    // all warps issued their final LDSM of this stage (lockstep
                    // code): safe to refill it with chunk i+2 under the MMAs.
                    __syncthreads();
                    int pf = i + 2;
                    if (pf < NC) load_tile(i % NST, pf * BK);
                    CP_COMMIT();
                }
                #pragma unroll
                for (int mt = 0; mt < MT; mt++)
                    #pragma unroll
                    for (int nt = 0; nt < NT; nt++) {
                        int p = nt >> 1, h = (nt & 1) << 1;
                        MMA16816F(acc[mt][nt],
                                  ar[cb][mt][0], ar[cb][mt][1], ar[cb][mt][2], ar[cb][mt][3],
                                  br[cb][p][h], br[cb][p][h + 1]);
                    }
            }
        } else {
            // single-buffered (low-reg) path: phased LDSM -> MMA per kk.
            static_assert(!DBUF ? NST >= 3 : true, "single-buffer path needs head prefetch");
            uint32_t ar[MT][4], br[PT][4];
            #pragma unroll
            for (int kk = 0; kk < NK; kk++) {
                const int s = 2 * kk;
                #pragma unroll
                for (int mt = 0; mt < MT; mt++) {
                    uint32_t ad = sa + a_rowb[mt] + (((s + a_hi) ^ a_rc[mt]) << 4);
                    LDSM4(ar[mt][0], ar[mt][1], ar[mt][2], ar[mt][3], ad);
                }
                #pragma unroll
                for (int p = 0; p < PT; p++) {
                    uint32_t bd = sB + b_rowb[p] + (((s + b_hi) ^ b_rc[p]) << 4);
                    LDSM4(br[p][0], br[p][1], br[p][2], br[p][3], bd);
                }
                #pragma unroll
                for (int mt = 0; mt < MT; mt++)
                    #pragma unroll
                    for (int nt = 0; nt < NT; nt++) {
                        int p = nt >> 1, h = (nt & 1) << 1;
                        MMA16816F(acc[mt][nt],
                                  ar[mt][0], ar[mt][1], ar[mt][2], ar[mt][3],
                                  br[p][h], br[p][h + 1]);
                    }
            }
        }
    }

    // ---------------- epilogue: fragments -> bias (+GELU) -> global ----------------
    const int mrow = lane >> 2;            // 0..7
    const int ncol = (lane & 3) * 2;       // 0,2,4,6
    #pragma unroll
    for (int mt = 0; mt < MT; mt++) {
        #pragma unroll
        for (int nt = 0; nt < NT; nt++) {
            int col_l = wn * WN + nt * 8 + ncol;
            float bi0 = bias_s[col_l], bi1 = bias_s[col_l + 1];
            #pragma unroll
            for (int half = 0; half < 2; half++) {   // d0d1 (m+0) / d2d3 (m+8)
                int row = m0 + wm * WM + mt * 16 + mrow + half * 8;
                float v0 = acc[mt][nt][2 * half]     + bi0;
                float v1 = acc[mt][nt][2 * half + 1] + bi1;
                if (GELU) {
                    v0 = 0.5f * v0 * (1.0f + erff(v0 * 0.70710678118654752f));
                    v1 = 0.5f * v1 * (1.0f + erff(v1 * 0.70710678118654752f));
                }
                size_t off = (size_t)row * Npar + n0 + col_l;
                if (GELU) {
                    __half2 h2 = __floats2half2_rn(v0, v1);
                    *reinterpret_cast<__half2*>(g_H + off) = h2;
                } else {
                    float2 f2; f2.x = v0; f2.y = v1;
                    *reinterpret_cast<float2*>(out_f + off) = f2;
                }
            }
        }
    }
}

// ---------------- preprocessing (3 launches) ----------------
__global__ void absmean_both_k(const float4* __restrict__ W1,
                               const float4* __restrict__ W2) {
    __shared__ float sm[256];
    const int half = blockIdx.x >> 10;               // 0: W1, 1: W2
    const int blk = blockIdx.x & 1023;
    const float4* w = half ? W2 : W1;
    float s = 0.f;
    const int total = WN_ / 4;
    for (int i = blk * 256 + threadIdx.x; i < total; i += 1024 * 256) {
        float4 v = w[i];
        s += fabsf(v.x) + fabsf(v.y) + fabsf(v.z) + fabsf(v.w);
    }
    sm[threadIdx.x] = s;
    __syncthreads();
    #pragma unroll
    for (int d = 128; d > 0; d >>= 1) {
        if (threadIdx.x < d) sm[threadIdx.x] += sm[threadIdx.x + d];
        __syncthreads();
    }
    if (threadIdx.x == 0) g_partial[half * 1024 + blk] = sm[0];
}

__global__ void absmean_final_k() {
    __shared__ float sm[1024];
    sm[threadIdx.x] = g_partial[blockIdx.x * 1024 + threadIdx.x];
    __syncthreads();
    #pragma unroll
    for (int d = 512; d > 0; d >>= 1) {
        if (threadIdx.x < d) sm[threadIdx.x] += sm[threadIdx.x + d];
        __syncthreads();
    }
    if (threadIdx.x == 0) g_scale[blockIdx.x] = fmaxf(sm[0] / (float)WN_, 1e-8f);
}

// one launch: quantize W1, W2 (ternary fp16) and convert x -> fp16
__global__ void prep_convert_k(const float4* __restrict__ W1,
                               const float4* __restrict__ W2,
                               const float4* __restrict__ x) {
    int i = blockIdx.x * 256 + threadIdx.x;
    const int Q = WN_ / 4;                   // 1M float4 per weight matrix
    uint2 u;
    if (i < 2 * Q) {
        int which = i >= Q;
        int j = i - which * Q;
        float inv = 1.0f / g_scale[which];
        float4 v = (which ? W2 : W1)[j];
        float a = fminf(fmaxf(rintf(v.x * inv), -1.f), 1.f);
        float b = fminf(fmaxf(rintf(v.y * inv), -1.f), 1.f);
        float c = fminf(fmaxf(rintf(v.z * inv), -1.f), 1.f);
        float d = fminf(fmaxf(rintf(v.w * inv), -1.f), 1.f);
        __half2 h0 = __floats2half2_rn(a, b);
        __half2 h1 = __floats2half2_rn(c, d);
        u.x = *reinterpret_cast<uint32_t*>(&h0);
        u.y = *reinterpret_cast<uint32_t*>(&h1);
        *reinterpret_cast<uint2*>((which ? g_W2t : g_W1t) + (size_t)j * 4) = u;
    } else {
        int j = i - 2 * Q;                  // 0 .. XN/4-1
        float4 v = x[j];
        __half2 h0 = __floats2half2_rn(v.x, v.y);
        __half2 h1 = __floats2half2_rn(v.z, v.w);
        u.x = *reinterpret_cast<uint32_t*>(&h0);
        u.y = *reinterpret_cast<uint32_t*>(&h1);
        *reinterpret_cast<uint2*>(g_Xh + (size_t)j * 4) = u;
    }
}

// ---------------- launcher ----------------
extern "C" void kernel_launch(void* const* d_in, const int* in_sizes, int n_in,
                              void* d_out, int out_size) {
    const float* x  = (const float*)d_in[0];
    const float* W1 = (const float*)d_in[1];
    const float* b1 = (const float*)d_in[2];
    const float* W2 = (const float*)d_in[3];
    const float* b2 = (const float*)d_in[4];
    float* out = (float*)d_out;

    // Both GEMMs: CTA 64x128, warp 32x32, BK=128, 2 stages, DBUF frags.
    // smem = 2048 + 2*49152 = 100352 -> 2 CTAs/SM; regs ~110 -> RF fits 2 CTAs.
    constexpr int SMEM = 2048 + 2 * (64 * 256 + 128 * 256);

    cudaFuncSetAttribute((const void*)ffn_gemm<64, 128, 32, 32, 128, 2, true, true>,
                         cudaFuncAttributeMaxDynamicSharedMemorySize, SMEM);
    cudaFuncSetAttribute((const void*)ffn_gemm<64, 128, 32, 32, 128, 2, true, false>,
                         cudaFuncAttributeMaxDynamicSharedMemorySize, SMEM);

    absmean_both_k<<<2048, 256>>>((const float4*)W1, (const float4*)W2);
    absmean_final_k<<<2, 1024>>>();
    prep_convert_k<<<(2 * (WN_ / 4) + XN_ / 4) / 256, 256>>>(
        (const float4*)W1, (const float4*)W2, (const float4*)x);

    // GEMM1: grid (4096/128, 8192/64) = 32 x 128 = 4096 CTAs (13.8 waves)
    ffn_gemm<64, 128, 32, 32, 128, 2, true, true>
        <<<dim3(FF / 128, NTOK / 64), 256, SMEM>>>(b1, nullptr);
    // GEMM2: grid (1024/128, 8192/64) = 8 x 128 = 1024 CTAs
    ffn_gemm<64, 128, 32, 32, 128, 2, true, false>
        <<<dim3(EMB / 128, NTOK / 64), 256, SMEM>>>(b2, out);
}